// round 3
// baseline (speedup 1.0000x reference)
#include <cuda_runtime.h>
#include <cuda_bf16.h>

// Sizes (fixed by the problem)
#define Bn   256
#define Tn   512
#define EMBn 64
#define HSn  512
#define VSn  128

// Launch shape: persistent kernel, one CTA per SM slot, all co-resident.
#define GRID   128
#define BLOCKT 256
#define KC     32     // K-chunk staged through SMEM
#define TM     32     // per-CTA tile rows (batch)
#define TN     32     // per-CTA tile cols (hidden units)
#define SPAD   36     // SMEM row stride (floats): 36*4=144B, 16B-aligned, bank-spread

// -------- persistent device state (static: no allocations, per the rules) ----
__device__ float g_h0[2][Bn * HSn];                       // ping-pong h0
__device__ float g_outs[(size_t)Tn * Bn * HSn];           // h1 history [t][b][hs]
__device__ float g_zero[Bn * HSn];                        // zeros for h1[-1]
__device__ unsigned g_count;                              // barrier arrivals
__device__ volatile unsigned g_phase;                     // barrier phase (monotonic)

// Software grid barrier (sense-free, phase counter; works across graph replays
// because only relative phase is observed and g_count returns to 0 each use).
__device__ __forceinline__ void grid_sync() {
    __syncthreads();
    if (threadIdx.x == 0) {
        __threadfence();                       // publish my writes
        unsigned ph = g_phase;
        if (atomicAdd(&g_count, 1u) == GRID - 1u) {
            g_count = 0u;
            __threadfence();
            g_phase = ph + 1u;                 // release
        } else {
            while (g_phase == ph) { }          // L2 spin (volatile)
            __threadfence();
        }
    }
    __syncthreads();
}

struct SmRec { float A[TM][SPAD]; float Bm[TN][SPAD]; };          // 9.2 KB
struct SmFc  { float A[64][SPAD]; float Bm[VSn][SPAD]; };         // 27.6 KB
union  Smem  { SmRec rec; SmFc fc; };

__global__ void __launch_bounds__(BLOCKT, 1) rnn_persistent_kernel(
    const int*   __restrict__ x,
    const float* __restrict__ emb,
    const float* __restrict__ W_ih0, const float* __restrict__ b_ih0,
    const float* __restrict__ W_hh0, const float* __restrict__ b_hh0,
    const float* __restrict__ W_ih1, const float* __restrict__ b_ih1,
    const float* __restrict__ W_hh1, const float* __restrict__ b_hh1,
    const float* __restrict__ W_fc,  const float* __restrict__ b_fc,
    float* __restrict__ out)
{
    __shared__ Smem sm;
    const int tid = threadIdx.x;
    const int cta = blockIdx.x;

    // ---- init: zero the t=-1 hidden states (re-done every launch: determinism)
    for (int i = cta * BLOCKT + tid; i < Bn * HSn; i += GRID * BLOCKT) {
        g_h0[1][i] = 0.f;
        g_zero[i]  = 0.f;
    }
    grid_sync();

    // Tile mapping: 8 row-tiles x 16 col-tiles = 128 CTAs
    const int row0 = (cta >> 4) * TM;     // batch rows
    const int col0 = (cta & 15) * TN;     // hidden cols
    // compute thread mapping: 16x16, 2x2 micro-tile
    const int ty  = tid >> 4;             // 0..15 (rows ty, ty+16)
    const int tx  = tid & 15;             // 0..15 (cols tx, tx+16)
    // loader mapping
    const int lkk = tid & 31;             // k lane (coalesced)
    const int lr  = tid >> 5;             // 0..7 row/k stride base

    const int c0 = col0 + tx, c1 = col0 + tx + 16;
    const int r0g = row0 + ty, r1g = row0 + ty + 16;
    const float bias0_0 = b_ih0[c0] + b_hh0[c0];
    const float bias0_1 = b_ih0[c1] + b_hh0[c1];
    const float bias1_0 = b_ih1[c0] + b_hh1[c0];
    const float bias1_1 = b_ih1[c1] + b_hh1[c1];

    for (int t = 0; t < Tn; ++t) {
        const float* h0_prev = g_h0[(t & 1) ^ 1];
        float*       h0_cur  = g_h0[t & 1];
        const float* h1_prev = (t == 0) ? g_zero : (g_outs + (size_t)(t - 1) * Bn * HSn);
        float*       h1_cur  = g_outs + (size_t)t * Bn * HSn;

        // ================= layer 0: h0 = tanh([emb|h0_prev] @ [Wih0;Whh0] + b)
        float a00 = 0.f, a01 = 0.f, a10 = 0.f, a11 = 0.f;
        #pragma unroll 1
        for (int k0 = 0; k0 < EMBn + HSn; k0 += KC) {
            __syncthreads();
            if (k0 < EMBn) {
                #pragma unroll
                for (int rr = lr; rr < TM; rr += 8) {
                    int xi = x[(row0 + rr) * Tn + t];
                    sm.rec.A[rr][lkk] = emb[xi * EMBn + k0 + lkk];
                }
            } else {
                #pragma unroll
                for (int rr = lr; rr < TM; rr += 8)
                    sm.rec.A[rr][lkk] =
                        __ldcg(&h0_prev[(row0 + rr) * HSn + (k0 - EMBn) + lkk]);
            }
            const float* Wb = (k0 < EMBn) ? (W_ih0 + (size_t)k0 * HSn)
                                          : (W_hh0 + (size_t)(k0 - EMBn) * HSn);
            #pragma unroll
            for (int kx = lr; kx < KC; kx += 8)
                sm.rec.Bm[lkk][kx] = Wb[(size_t)kx * HSn + col0 + lkk];
            __syncthreads();
            #pragma unroll
            for (int k4 = 0; k4 < KC; k4 += 4) {
                float4 av0 = *(const float4*)&sm.rec.A[ty][k4];
                float4 av1 = *(const float4*)&sm.rec.A[ty + 16][k4];
                float4 bv0 = *(const float4*)&sm.rec.Bm[tx][k4];
                float4 bv1 = *(const float4*)&sm.rec.Bm[tx + 16][k4];
                a00 += av0.x*bv0.x; a00 += av0.y*bv0.y; a00 += av0.z*bv0.z; a00 += av0.w*bv0.w;
                a01 += av0.x*bv1.x; a01 += av0.y*bv1.y; a01 += av0.z*bv1.z; a01 += av0.w*bv1.w;
                a10 += av1.x*bv0.x; a10 += av1.y*bv0.y; a10 += av1.z*bv0.z; a10 += av1.w*bv0.w;
                a11 += av1.x*bv1.x; a11 += av1.y*bv1.y; a11 += av1.z*bv1.z; a11 += av1.w*bv1.w;
            }
        }
        h0_cur[r0g * HSn + c0] = tanhf(a00 + bias0_0);
        h0_cur[r0g * HSn + c1] = tanhf(a01 + bias0_1);
        h0_cur[r1g * HSn + c0] = tanhf(a10 + bias0_0);
        h0_cur[r1g * HSn + c1] = tanhf(a11 + bias0_1);
        grid_sync();   // h0_cur complete for all columns

        // ================= layer 1: h1 = tanh([h0_cur|h1_prev] @ [Wih1;Whh1] + b)
        float d00 = 0.f, d01 = 0.f, d10 = 0.f, d11 = 0.f;
        #pragma unroll 1
        for (int k0 = 0; k0 < 2 * HSn; k0 += KC) {
            __syncthreads();
            const float* Asrc = (k0 < HSn) ? h0_cur : h1_prev;
            const int ka = (k0 < HSn) ? k0 : (k0 - HSn);
            #pragma unroll
            for (int rr = lr; rr < TM; rr += 8)
                sm.rec.A[rr][lkk] = __ldcg(&Asrc[(row0 + rr) * HSn + ka + lkk]);
            const float* Wb = (k0 < HSn) ? (W_ih1 + (size_t)k0 * HSn)
                                         : (W_hh1 + (size_t)(k0 - HSn) * HSn);
            #pragma unroll
            for (int kx = lr; kx < KC; kx += 8)
                sm.rec.Bm[lkk][kx] = Wb[(size_t)kx * HSn + col0 + lkk];
            __syncthreads();
            #pragma unroll
            for (int k4 = 0; k4 < KC; k4 += 4) {
                float4 av0 = *(const float4*)&sm.rec.A[ty][k4];
                float4 av1 = *(const float4*)&sm.rec.A[ty + 16][k4];
                float4 bv0 = *(const float4*)&sm.rec.Bm[tx][k4];
                float4 bv1 = *(const float4*)&sm.rec.Bm[tx + 16][k4];
                d00 += av0.x*bv0.x; d00 += av0.y*bv0.y; d00 += av0.z*bv0.z; d00 += av0.w*bv0.w;
                d01 += av0.x*bv1.x; d01 += av0.y*bv1.y; d01 += av0.z*bv1.z; d01 += av0.w*bv1.w;
                d10 += av1.x*bv0.x; d10 += av1.y*bv0.y; d10 += av1.z*bv0.z; d10 += av1.w*bv0.w;
                d11 += av1.x*bv1.x; d11 += av1.y*bv1.y; d11 += av1.z*bv1.z; d11 += av1.w*bv1.w;
            }
        }
        h1_cur[r0g * HSn + c0] = tanhf(d00 + bias1_0);
        h1_cur[r0g * HSn + c1] = tanhf(d01 + bias1_1);
        h1_cur[r1g * HSn + c0] = tanhf(d10 + bias1_0);
        h1_cur[r1g * HSn + c1] = tanhf(d11 + bias1_1);
        grid_sync();   // h1_cur complete before next step / FC
    }

    // ================= final FC: logits[b,t,:] = h1[t,b,:] @ W_fc + b_fc
    // M = T*B = 131072 rows (row m = t*256 + b), N = 128, K = 512.
    const int fty = tid >> 5;      // 0..7  (rows fty + 8*i, warp-uniform -> broadcast A reads)
    const int ftx = tid & 31;      // 0..31 (cols ftx + 32*j)
    const int fj  = tid & 127;     // B loader col
    const int fkk = tid >> 7;      // B loader k base (0..1)
    const int NTILES = (Bn * Tn) / 64;     // 2048 tiles of 64 rows
    for (int tile = cta; tile < NTILES; tile += GRID) {
        const int m0 = tile * 64;
        float acc[8][4];
        #pragma unroll
        for (int ii = 0; ii < 8; ++ii)
            #pragma unroll
            for (int jj = 0; jj < 4; ++jj) acc[ii][jj] = 0.f;

        #pragma unroll 1
        for (int k0 = 0; k0 < HSn; k0 += KC) {
            __syncthreads();
            #pragma unroll
            for (int rr = lr; rr < 64; rr += 8)
                sm.fc.A[rr][lkk] = g_outs[(size_t)(m0 + rr) * HSn + k0 + lkk];
            #pragma unroll
            for (int kx = fkk; kx < KC; kx += 2)
                sm.fc.Bm[fj][kx] = W_fc[(size_t)(k0 + kx) * VSn + fj];
            __syncthreads();
            #pragma unroll
            for (int k4 = 0; k4 < KC; k4 += 4) {
                float4 bv[4];
                #pragma unroll
                for (int jj = 0; jj < 4; ++jj)
                    bv[jj] = *(const float4*)&sm.fc.Bm[ftx + 32 * jj][k4];
                #pragma unroll
                for (int ii = 0; ii < 8; ++ii) {
                    float4 av = *(const float4*)&sm.fc.A[fty + 8 * ii][k4];
                    #pragma unroll
                    for (int jj = 0; jj < 4; ++jj) {
                        acc[ii][jj] += av.x * bv[jj].x;
                        acc[ii][jj] += av.y * bv[jj].y;
                        acc[ii][jj] += av.z * bv[jj].z;
                        acc[ii][jj] += av.w * bv[jj].w;
                    }
                }
            }
        }
        #pragma unroll
        for (int ii = 0; ii < 8; ++ii) {
            const int m  = m0 + fty + 8 * ii;
            const int tt = m >> 8;        // t = m / 256
            const int bb = m & 255;       // b = m % 256
            float* op = out + ((size_t)bb * Tn + tt) * VSn;
            #pragma unroll
            for (int jj = 0; jj < 4; ++jj) {
                const int c = ftx + 32 * jj;
                op[c] = acc[ii][jj] + b_fc[c];
            }
        }
        __syncthreads();   // protect SMEM before next tile's loads
    }
}

extern "C" void kernel_launch(void* const* d_in, const int* in_sizes, int n_in,
                              void* d_out, int out_size) {
    const int*   x      = (const int*)  d_in[0];
    const float* emb    = (const float*)d_in[1];
    const float* W_ih0  = (const float*)d_in[2];
    const float* b_ih0  = (const float*)d_in[3];
    const float* W_hh0  = (const float*)d_in[4];
    const float* b_hh0  = (const float*)d_in[5];
    const float* W_ih1  = (const float*)d_in[6];
    const float* b_ih1  = (const float*)d_in[7];
    const float* W_hh1  = (const float*)d_in[8];
    const float* b_hh1  = (const float*)d_in[9];
    const float* W_fc   = (const float*)d_in[10];
    const float* b_fc   = (const float*)d_in[11];
    float* out = (float*)d_out;

    rnn_persistent_kernel<<<GRID, BLOCKT>>>(
        x, emb, W_ih0, b_ih0, W_hh0, b_hh0,
        W_ih1, b_ih1, W_hh1, b_hh1, W_fc, b_fc, out);
}

// round 4
// speedup vs baseline: 1.0031x; 1.0031x over previous
#include <cuda_runtime.h>
#include <cuda_bf16.h>

// Sizes (fixed by the problem)
#define Bn   256
#define Tn   512
#define EMBn 64
#define HSn  512
#define VSn  128

// Launch shape: persistent kernel, one CTA per SM slot, all co-resident.
#define GRID   128
#define BLOCKT 256
#define KC     32     // K-chunk staged through SMEM
#define TM     32     // per-CTA tile rows (batch)
#define TN     32     // per-CTA tile cols (hidden units)
#define SPAD   36     // SMEM row stride (floats): 36*4=144B, 16B-aligned, bank-spread

// -------- persistent device state (static: no allocations, per the rules) ----
__device__ float g_h0[2][Bn * HSn];                       // ping-pong h0
__device__ float g_outs[(size_t)Tn * Bn * HSn];           // h1 history [t][b][hs]
__device__ float g_zero[Bn * HSn];                        // zeros for h1[-1]
__device__ unsigned g_count;                              // barrier arrivals
__device__ volatile unsigned g_phase;                     // barrier phase (monotonic)

// Software grid barrier (sense-free, phase counter; works across graph replays
// because only relative phase is observed and g_count returns to 0 each use).
__device__ __forceinline__ void grid_sync() {
    __syncthreads();
    if (threadIdx.x == 0) {
        __threadfence();                       // publish my writes
        unsigned ph = g_phase;
        if (atomicAdd(&g_count, 1u) == GRID - 1u) {
            g_count = 0u;
            __threadfence();
            g_phase = ph + 1u;                 // release
        } else {
            while (g_phase == ph) { }          // L2 spin (volatile)
            __threadfence();
        }
    }
    __syncthreads();
}

struct SmRec { float A[TM][SPAD]; float Bm[TN][SPAD]; };          // 9.2 KB
struct SmFc  { float A[64][SPAD]; float Bm[VSn][SPAD]; };         // 27.6 KB
union  Smem  { SmRec rec; SmFc fc; };

__global__ void __launch_bounds__(BLOCKT, 1) rnn_persistent_kernel(
    const int*   __restrict__ x,
    const float* __restrict__ emb,
    const float* __restrict__ W_ih0, const float* __restrict__ b_ih0,
    const float* __restrict__ W_hh0, const float* __restrict__ b_hh0,
    const float* __restrict__ W_ih1, const float* __restrict__ b_ih1,
    const float* __restrict__ W_hh1, const float* __restrict__ b_hh1,
    const float* __restrict__ W_fc,  const float* __restrict__ b_fc,
    float* __restrict__ out)
{
    __shared__ Smem sm;
    const int tid = threadIdx.x;
    const int cta = blockIdx.x;

    // ---- init: zero the t=-1 hidden states (re-done every launch: determinism)
    for (int i = cta * BLOCKT + tid; i < Bn * HSn; i += GRID * BLOCKT) {
        g_h0[1][i] = 0.f;
        g_zero[i]  = 0.f;
    }
    grid_sync();

    // Tile mapping: 8 row-tiles x 16 col-tiles = 128 CTAs
    const int row0 = (cta >> 4) * TM;     // batch rows
    const int col0 = (cta & 15) * TN;     // hidden cols
    // compute thread mapping: 16x16, 2x2 micro-tile
    const int ty  = tid >> 4;             // 0..15 (rows ty, ty+16)
    const int tx  = tid & 15;             // 0..15 (cols tx, tx+16)
    // loader mapping
    const int lkk = tid & 31;             // k lane (coalesced)
    const int lr  = tid >> 5;             // 0..7 row/k stride base

    const int c0 = col0 + tx, c1 = col0 + tx + 16;
    const int r0g = row0 + ty, r1g = row0 + ty + 16;
    const float bias0_0 = b_ih0[c0] + b_hh0[c0];
    const float bias0_1 = b_ih0[c1] + b_hh0[c1];
    const float bias1_0 = b_ih1[c0] + b_hh1[c0];
    const float bias1_1 = b_ih1[c1] + b_hh1[c1];

    for (int t = 0; t < Tn; ++t) {
        const float* h0_prev = g_h0[(t & 1) ^ 1];
        float*       h0_cur  = g_h0[t & 1];
        const float* h1_prev = (t == 0) ? g_zero : (g_outs + (size_t)(t - 1) * Bn * HSn);
        float*       h1_cur  = g_outs + (size_t)t * Bn * HSn;

        // ================= layer 0: h0 = tanh([emb|h0_prev] @ [Wih0;Whh0] + b)
        float a00 = 0.f, a01 = 0.f, a10 = 0.f, a11 = 0.f;
        #pragma unroll 1
        for (int k0 = 0; k0 < EMBn + HSn; k0 += KC) {
            __syncthreads();
            if (k0 < EMBn) {
                #pragma unroll
                for (int rr = lr; rr < TM; rr += 8) {
                    int xi = x[(row0 + rr) * Tn + t];
                    sm.rec.A[rr][lkk] = emb[xi * EMBn + k0 + lkk];
                }
            } else {
                #pragma unroll
                for (int rr = lr; rr < TM; rr += 8)
                    sm.rec.A[rr][lkk] =
                        __ldcg(&h0_prev[(row0 + rr) * HSn + (k0 - EMBn) + lkk]);
            }
            const float* Wb = (k0 < EMBn) ? (W_ih0 + (size_t)k0 * HSn)
                                          : (W_hh0 + (size_t)(k0 - EMBn) * HSn);
            #pragma unroll
            for (int kx = lr; kx < KC; kx += 8)
                sm.rec.Bm[lkk][kx] = Wb[(size_t)kx * HSn + col0 + lkk];
            __syncthreads();
            #pragma unroll
            for (int k4 = 0; k4 < KC; k4 += 4) {
                float4 av0 = *(const float4*)&sm.rec.A[ty][k4];
                float4 av1 = *(const float4*)&sm.rec.A[ty + 16][k4];
                float4 bv0 = *(const float4*)&sm.rec.Bm[tx][k4];
                float4 bv1 = *(const float4*)&sm.rec.Bm[tx + 16][k4];
                a00 += av0.x*bv0.x; a00 += av0.y*bv0.y; a00 += av0.z*bv0.z; a00 += av0.w*bv0.w;
                a01 += av0.x*bv1.x; a01 += av0.y*bv1.y; a01 += av0.z*bv1.z; a01 += av0.w*bv1.w;
                a10 += av1.x*bv0.x; a10 += av1.y*bv0.y; a10 += av1.z*bv0.z; a10 += av1.w*bv0.w;
                a11 += av1.x*bv1.x; a11 += av1.y*bv1.y; a11 += av1.z*bv1.z; a11 += av1.w*bv1.w;
            }
        }
        h0_cur[r0g * HSn + c0] = tanhf(a00 + bias0_0);
        h0_cur[r0g * HSn + c1] = tanhf(a01 + bias0_1);
        h0_cur[r1g * HSn + c0] = tanhf(a10 + bias0_0);
        h0_cur[r1g * HSn + c1] = tanhf(a11 + bias0_1);
        grid_sync();   // h0_cur complete for all columns

        // ================= layer 1: h1 = tanh([h0_cur|h1_prev] @ [Wih1;Whh1] + b)
        float d00 = 0.f, d01 = 0.f, d10 = 0.f, d11 = 0.f;
        #pragma unroll 1
        for (int k0 = 0; k0 < 2 * HSn; k0 += KC) {
            __syncthreads();
            const float* Asrc = (k0 < HSn) ? h0_cur : h1_prev;
            const int ka = (k0 < HSn) ? k0 : (k0 - HSn);
            #pragma unroll
            for (int rr = lr; rr < TM; rr += 8)
                sm.rec.A[rr][lkk] = __ldcg(&Asrc[(row0 + rr) * HSn + ka + lkk]);
            const float* Wb = (k0 < HSn) ? (W_ih1 + (size_t)k0 * HSn)
                                         : (W_hh1 + (size_t)(k0 - HSn) * HSn);
            #pragma unroll
            for (int kx = lr; kx < KC; kx += 8)
                sm.rec.Bm[lkk][kx] = Wb[(size_t)kx * HSn + col0 + lkk];
            __syncthreads();
            #pragma unroll
            for (int k4 = 0; k4 < KC; k4 += 4) {
                float4 av0 = *(const float4*)&sm.rec.A[ty][k4];
                float4 av1 = *(const float4*)&sm.rec.A[ty + 16][k4];
                float4 bv0 = *(const float4*)&sm.rec.Bm[tx][k4];
                float4 bv1 = *(const float4*)&sm.rec.Bm[tx + 16][k4];
                d00 += av0.x*bv0.x; d00 += av0.y*bv0.y; d00 += av0.z*bv0.z; d00 += av0.w*bv0.w;
                d01 += av0.x*bv1.x; d01 += av0.y*bv1.y; d01 += av0.z*bv1.z; d01 += av0.w*bv1.w;
                d10 += av1.x*bv0.x; d10 += av1.y*bv0.y; d10 += av1.z*bv0.z; d10 += av1.w*bv0.w;
                d11 += av1.x*bv1.x; d11 += av1.y*bv1.y; d11 += av1.z*bv1.z; d11 += av1.w*bv1.w;
            }
        }
        h1_cur[r0g * HSn + c0] = tanhf(d00 + bias1_0);
        h1_cur[r0g * HSn + c1] = tanhf(d01 + bias1_1);
        h1_cur[r1g * HSn + c0] = tanhf(d10 + bias1_0);
        h1_cur[r1g * HSn + c1] = tanhf(d11 + bias1_1);
        grid_sync();   // h1_cur complete before next step / FC
    }

    // ================= final FC: logits[b,t,:] = h1[t,b,:] @ W_fc + b_fc
    // M = T*B = 131072 rows (row m = t*256 + b), N = 128, K = 512.
    const int fty = tid >> 5;      // 0..7  (rows fty + 8*i, warp-uniform -> broadcast A reads)
    const int ftx = tid & 31;      // 0..31 (cols ftx + 32*j)
    const int fj  = tid & 127;     // B loader col
    const int fkk = tid >> 7;      // B loader k base (0..1)
    const int NTILES = (Bn * Tn) / 64;     // 2048 tiles of 64 rows
    for (int tile = cta; tile < NTILES; tile += GRID) {
        const int m0 = tile * 64;
        float acc[8][4];
        #pragma unroll
        for (int ii = 0; ii < 8; ++ii)
            #pragma unroll
            for (int jj = 0; jj < 4; ++jj) acc[ii][jj] = 0.f;

        #pragma unroll 1
        for (int k0 = 0; k0 < HSn; k0 += KC) {
            __syncthreads();
            #pragma unroll
            for (int rr = lr; rr < 64; rr += 8)
                sm.fc.A[rr][lkk] = g_outs[(size_t)(m0 + rr) * HSn + k0 + lkk];
            #pragma unroll
            for (int kx = fkk; kx < KC; kx += 2)
                sm.fc.Bm[fj][kx] = W_fc[(size_t)(k0 + kx) * VSn + fj];
            __syncthreads();
            #pragma unroll
            for (int k4 = 0; k4 < KC; k4 += 4) {
                float4 bv[4];
                #pragma unroll
                for (int jj = 0; jj < 4; ++jj)
                    bv[jj] = *(const float4*)&sm.fc.Bm[ftx + 32 * jj][k4];
                #pragma unroll
                for (int ii = 0; ii < 8; ++ii) {
                    float4 av = *(const float4*)&sm.fc.A[fty + 8 * ii][k4];
                    #pragma unroll
                    for (int jj = 0; jj < 4; ++jj) {
                        acc[ii][jj] += av.x * bv[jj].x;
                        acc[ii][jj] += av.y * bv[jj].y;
                        acc[ii][jj] += av.z * bv[jj].z;
                        acc[ii][jj] += av.w * bv[jj].w;
                    }
                }
            }
        }
        #pragma unroll
        for (int ii = 0; ii < 8; ++ii) {
            const int m  = m0 + fty + 8 * ii;
            const int tt = m >> 8;        // t = m / 256
            const int bb = m & 255;       // b = m % 256
            float* op = out + ((size_t)bb * Tn + tt) * VSn;
            #pragma unroll
            for (int jj = 0; jj < 4; ++jj) {
                const int c = ftx + 32 * jj;
                op[c] = acc[ii][jj] + b_fc[c];
            }
        }
        __syncthreads();   // protect SMEM before next tile's loads
    }
}

extern "C" void kernel_launch(void* const* d_in, const int* in_sizes, int n_in,
                              void* d_out, int out_size) {
    const int*   x      = (const int*)  d_in[0];
    const float* emb    = (const float*)d_in[1];
    const float* W_ih0  = (const float*)d_in[2];
    const float* b_ih0  = (const float*)d_in[3];
    const float* W_hh0  = (const float*)d_in[4];
    const float* b_hh0  = (const float*)d_in[5];
    const float* W_ih1  = (const float*)d_in[6];
    const float* b_ih1  = (const float*)d_in[7];
    const float* W_hh1  = (const float*)d_in[8];
    const float* b_hh1  = (const float*)d_in[9];
    const float* W_fc   = (const float*)d_in[10];
    const float* b_fc   = (const float*)d_in[11];
    float* out = (float*)d_out;

    rnn_persistent_kernel<<<GRID, BLOCKT>>>(
        x, emb, W_ih0, b_ih0, W_hh0, b_hh0,
        W_ih1, b_ih1, W_hh1, b_hh1, W_fc, b_fc, out);
}

// round 5
// speedup vs baseline: 2.7239x; 2.7155x over previous
#include <cuda_runtime.h>

// Problem sizes
#define Bn   256
#define Tn   512
#define EMBn 64
#define HSn  512
#define VSn  128

// Shape: 8 row-groups (32 batch rows each) x 16 col-tiles (32 hidden cols) = 128 CTAs
#define GRID   128
#define NGROUP 8
#define GSIZE  16
#define BLOCKT 256
#define KC     64          // K-chunk staged through SMEM
#define KTOT   1600        // concat K: Wih0(64)+Whh0(512)+Wih1(512)+Whh1(512)
#define WPAD   1604        // Wt row stride (floats), 16B aligned
#define APAD   68          // A buffer row stride (floats), 16B aligned
#define FCPAD  36          // FC smem stride

#define SMEM_FLOATS (32 * WPAD + 2 * 32 * APAD)
#define SMEM_BYTES  (SMEM_FLOATS * 4)        // 222,720 B

// -------- persistent device state (no allocations; __device__ globals) -------
__device__ float g_h0[2][Bn * HSn];                 // ping-pong h0
__device__ float g_outs[(size_t)Tn * Bn * HSn];     // h1 history [t][b][hs]
struct PadCnt { unsigned v; unsigned pad[31]; };
__device__ PadCnt g_gcnt[NGROUP];                   // per-group arrival counters
__device__ volatile unsigned g_gphase[NGROUP * 32]; // per-group phase (strided 128B)
__device__ unsigned g_allcnt;                       // full-grid barrier
__device__ volatile unsigned g_allphase;

// Group barrier: 16 CTAs. Publish (fence all threads) -> arrive -> spin on phase.
__device__ __forceinline__ void group_sync(int g) {
    __threadfence();
    __syncthreads();
    if (threadIdx.x == 0) {
        unsigned ph = g_gphase[g * 32];
        if (atomicAdd(&g_gcnt[g].v, 1u) == GSIZE - 1u) {
            g_gcnt[g].v = 0u;
            __threadfence();
            g_gphase[g * 32] = ph + 1u;
        } else {
            while (g_gphase[g * 32] == ph) { }
        }
    }
    __syncthreads();
}

__device__ __forceinline__ void grid_sync_all() {
    __threadfence();
    __syncthreads();
    if (threadIdx.x == 0) {
        unsigned ph = g_allphase;
        if (atomicAdd(&g_allcnt, 1u) == GRID - 1u) {
            g_allcnt = 0u;
            __threadfence();
            g_allphase = ph + 1u;
        } else {
            while (g_allphase == ph) { }
        }
    }
    __syncthreads();
}

#define FMA4(acc, av, bv) { acc += av.x*bv.x; acc += av.y*bv.y; \
                            acc += av.z*bv.z; acc += av.w*bv.w; }

// One KC=64 chunk: 2x2 micro-tile, A from SMEM buffer, B from resident weights.
__device__ __forceinline__ void chunk_fma(const float* __restrict__ Ac,
                                          const float* __restrict__ W0,
                                          const float* __restrict__ W1,
                                          int ty,
                                          float& a00, float& a01,
                                          float& a10, float& a11) {
    #pragma unroll
    for (int k4 = 0; k4 < KC; k4 += 4) {
        float4 av0 = *(const float4*)(Ac + ty * APAD + k4);
        float4 av1 = *(const float4*)(Ac + (ty + 16) * APAD + k4);
        float4 bv0 = *(const float4*)(W0 + k4);
        float4 bv1 = *(const float4*)(W1 + k4);
        FMA4(a00, av0, bv0); FMA4(a01, av0, bv1);
        FMA4(a10, av1, bv0); FMA4(a11, av1, bv1);
    }
}

extern __shared__ float smem[];

__global__ void __launch_bounds__(BLOCKT, 1) rnn_persistent_kernel(
    const int*   __restrict__ x,
    const float* __restrict__ emb,
    const float* __restrict__ W_ih0, const float* __restrict__ b_ih0,
    const float* __restrict__ W_hh0, const float* __restrict__ b_hh0,
    const float* __restrict__ W_ih1, const float* __restrict__ b_ih1,
    const float* __restrict__ W_hh1, const float* __restrict__ b_hh1,
    const float* __restrict__ W_fc,  const float* __restrict__ b_fc,
    float* __restrict__ out)
{
    float* Wt = smem;                      // [32][WPAD] resident weight slice
    float* Ab = smem + 32 * WPAD;          // [2][32][APAD] A double buffer

    const int tid  = threadIdx.x;
    const int cta  = blockIdx.x;
    const int grp  = cta >> 4;
    const int row0 = grp * 32;             // batch rows owned by this group
    const int col0 = (cta & 15) * 32;      // hidden cols owned by this CTA

    // ---- load the CTA's weight slice once: Wt[c][k], k = concat index -------
    {
        const int c  = tid & 31;
        const int k8 = tid >> 5;
        for (int kb = 0; kb < KTOT; kb += 8) {
            int k = kb + k8;
            const float* src; int kr;
            if      (k < 64)   { src = W_ih0; kr = k; }
            else if (k < 576)  { src = W_hh0; kr = k - 64; }
            else if (k < 1088) { src = W_ih1; kr = k - 576; }
            else               { src = W_hh1; kr = k - 1088; }
            Wt[c * WPAD + k] = src[(size_t)kr * HSn + col0 + c];
        }
    }
    __syncthreads();

    // compute mapping (16x16 threads, 2x2 micro-tile); loader shares indices
    const int ty  = tid >> 4;              // 0..15 -> rows ty, ty+16
    const int tx  = tid & 15;              // 0..15 -> cols tx, tx+16
    const int ak4 = (tid & 15) * 4;        // A loader k offset (float4)

    const int r0g = row0 + ty, r1g = row0 + ty + 16;
    const int c0  = col0 + tx, c1  = col0 + tx + 16;
    const float bias0_0 = b_ih0[c0] + b_hh0[c0];
    const float bias0_1 = b_ih0[c1] + b_hh0[c1];
    const float bias1_0 = b_ih1[c0] + b_hh1[c0];
    const float bias1_1 = b_ih1[c1] + b_hh1[c1];

    const float* W0a = Wt + tx * WPAD;
    const float* W1a = Wt + (tx + 16) * WPAD;

    for (int t = 0; t < Tn; ++t) {
        const float* h0_prev = g_h0[(t & 1) ^ 1];
        float*       h0_cur  = g_h0[t & 1];
        const float* h1_prev = g_outs + (size_t)(t - 1) * Bn * HSn;  // valid t>0
        float*       h1_cur  = g_outs + (size_t)t * Bn * HSn;

        // =========== layer 0: h0 = tanh([emb | h0_prev] @ [Wih0;Whh0] + b)
        {
            const int nch = (t == 0) ? 1 : 9;   // t=0: h0_prev is zero, skip
            float4 p0, p1;
            // prologue: chunk 0 = embedding rows
            {
                int xi0 = x[r0g * Tn + t];
                int xi1 = x[r1g * Tn + t];
                p0 = *(const float4*)&emb[xi0 * EMBn + ak4];
                p1 = *(const float4*)&emb[xi1 * EMBn + ak4];
            }
            *(float4*)&Ab[ty * APAD + ak4]        = p0;
            *(float4*)&Ab[(ty + 16) * APAD + ak4] = p1;
            __syncthreads();

            float a00 = 0.f, a01 = 0.f, a10 = 0.f, a11 = 0.f;
            int buf = 0;
            #pragma unroll 1
            for (int c = 0; c < nch; ++c) {
                if (c + 1 < nch) {
                    int kb = c * KC;   // chunk c+1 covers h0_prev[k = c*64 ..]
                    p0 = __ldcg((const float4*)&h0_prev[(size_t)r0g * HSn + kb + ak4]);
                    p1 = __ldcg((const float4*)&h0_prev[(size_t)r1g * HSn + kb + ak4]);
                }
                chunk_fma(Ab + buf * 32 * APAD, W0a + c * KC, W1a + c * KC,
                          ty, a00, a01, a10, a11);
                if (c + 1 < nch) {
                    float* An = Ab + (buf ^ 1) * 32 * APAD;
                    *(float4*)&An[ty * APAD + ak4]        = p0;
                    *(float4*)&An[(ty + 16) * APAD + ak4] = p1;
                }
                __syncthreads();
                buf ^= 1;
            }
            h0_cur[(size_t)r0g * HSn + c0] = tanhf(a00 + bias0_0);
            h0_cur[(size_t)r0g * HSn + c1] = tanhf(a01 + bias0_1);
            h0_cur[(size_t)r1g * HSn + c0] = tanhf(a10 + bias0_0);
            h0_cur[(size_t)r1g * HSn + c1] = tanhf(a11 + bias0_1);
        }
        group_sync(grp);   // h0_cur complete within group (also orders prev L1)

        // =========== layer 1: h1 = tanh([h0_cur | h1_prev] @ [Wih1;Whh1] + b)
        {
            const int nch = (t == 0) ? 8 : 16;  // t=0: h1_prev is zero, skip
            float4 p0, p1;
            p0 = __ldcg((const float4*)&h0_cur[(size_t)r0g * HSn + ak4]);
            p1 = __ldcg((const float4*)&h0_cur[(size_t)r1g * HSn + ak4]);
            *(float4*)&Ab[ty * APAD + ak4]        = p0;
            *(float4*)&Ab[(ty + 16) * APAD + ak4] = p1;
            __syncthreads();

            float d00 = 0.f, d01 = 0.f, d10 = 0.f, d11 = 0.f;
            int buf = 0;
            #pragma unroll 1
            for (int c = 0; c < nch; ++c) {
                if (c + 1 < nch) {
                    const float* hs = (c + 1 < 8) ? h0_cur : h1_prev;
                    int kb = (c + 1 < 8) ? (c + 1) * KC : (c + 1 - 8) * KC;
                    p0 = __ldcg((const float4*)&hs[(size_t)r0g * HSn + kb + ak4]);
                    p1 = __ldcg((const float4*)&hs[(size_t)r1g * HSn + kb + ak4]);
                }
                chunk_fma(Ab + buf * 32 * APAD,
                          W0a + 576 + c * KC, W1a + 576 + c * KC,
                          ty, d00, d01, d10, d11);
                if (c + 1 < nch) {
                    float* An = Ab + (buf ^ 1) * 32 * APAD;
                    *(float4*)&An[ty * APAD + ak4]        = p0;
                    *(float4*)&An[(ty + 16) * APAD + ak4] = p1;
                }
                __syncthreads();
                buf ^= 1;
            }
            h1_cur[(size_t)r0g * HSn + c0] = tanhf(d00 + bias1_0);
            h1_cur[(size_t)r0g * HSn + c1] = tanhf(d01 + bias1_1);
            h1_cur[(size_t)r1g * HSn + c0] = tanhf(d10 + bias1_0);
            h1_cur[(size_t)r1g * HSn + c1] = tanhf(d11 + bias1_1);
        }
        // NOTE: no barrier here — next step's post-L0 group_sync transitively
        // orders these h1 writes before any step-t+1 L1 reads.
    }

    grid_sync_all();   // all h1 history visible chip-wide before FC

    // =========== final FC: logits[b,t,:] = h1[t,b,:] @ W_fc + b_fc ==========
    // M = T*B rows (m = t*256 + b), N = 128, K = 512. Reuse SMEM (weights dead).
    float* fcA = smem;                 // [64][FCPAD]
    float* fcB = smem + 64 * FCPAD;    // [128][FCPAD]

    const int lkk = tid & 31;
    const int lr  = tid >> 5;
    const int fty = tid >> 5;          // 0..7
    const int ftx = tid & 31;          // 0..31
    const int fj  = tid & 127;
    const int fkk = tid >> 7;
    const int NTILES = (Bn * Tn) / 64;

    for (int tile = cta; tile < NTILES; tile += GRID) {
        const int m0 = tile * 64;
        float acc[8][4];
        #pragma unroll
        for (int ii = 0; ii < 8; ++ii)
            #pragma unroll
            for (int jj = 0; jj < 4; ++jj) acc[ii][jj] = 0.f;

        #pragma unroll 1
        for (int k0 = 0; k0 < HSn; k0 += 32) {
            __syncthreads();
            #pragma unroll
            for (int rr = lr; rr < 64; rr += 8)
                fcA[rr * FCPAD + lkk] =
                    g_outs[(size_t)(m0 + rr) * HSn + k0 + lkk];
            #pragma unroll
            for (int kx = fkk; kx < 32; kx += 2)
                fcB[fj * FCPAD + kx] = W_fc[(size_t)(k0 + kx) * VSn + fj];
            __syncthreads();
            #pragma unroll
            for (int k4 = 0; k4 < 32; k4 += 4) {
                float4 bv[4];
                #pragma unroll
                for (int jj = 0; jj < 4; ++jj)
                    bv[jj] = *(const float4*)&fcB[(ftx + 32 * jj) * FCPAD + k4];
                #pragma unroll
                for (int ii = 0; ii < 8; ++ii) {
                    float4 av = *(const float4*)&fcA[(fty + 8 * ii) * FCPAD + k4];
                    #pragma unroll
                    for (int jj = 0; jj < 4; ++jj) {
                        acc[ii][jj] += av.x * bv[jj].x;
                        acc[ii][jj] += av.y * bv[jj].y;
                        acc[ii][jj] += av.z * bv[jj].z;
                        acc[ii][jj] += av.w * bv[jj].w;
                    }
                }
            }
        }
        #pragma unroll
        for (int ii = 0; ii < 8; ++ii) {
            const int m  = m0 + fty + 8 * ii;
            const int tt = m >> 8;
            const int bb = m & 255;
            float* op = out + ((size_t)bb * Tn + tt) * VSn;
            #pragma unroll
            for (int jj = 0; jj < 4; ++jj) {
                const int c = ftx + 32 * jj;
                op[c] = acc[ii][jj] + b_fc[c];
            }
        }
        __syncthreads();
    }
}

extern "C" void kernel_launch(void* const* d_in, const int* in_sizes, int n_in,
                              void* d_out, int out_size) {
    const int*   x      = (const int*)  d_in[0];
    const float* emb    = (const float*)d_in[1];
    const float* W_ih0  = (const float*)d_in[2];
    const float* b_ih0  = (const float*)d_in[3];
    const float* W_hh0  = (const float*)d_in[4];
    const float* b_hh0  = (const float*)d_in[5];
    const float* W_ih1  = (const float*)d_in[6];
    const float* b_ih1  = (const float*)d_in[7];
    const float* W_hh1  = (const float*)d_in[8];
    const float* b_hh1  = (const float*)d_in[9];
    const float* W_fc   = (const float*)d_in[10];
    const float* b_fc   = (const float*)d_in[11];
    float* out = (float*)d_out;

    cudaFuncSetAttribute(rnn_persistent_kernel,
                         cudaFuncAttributeMaxDynamicSharedMemorySize, SMEM_BYTES);

    rnn_persistent_kernel<<<GRID, BLOCKT, SMEM_BYTES>>>(
        x, emb, W_ih0, b_ih0, W_hh0, b_hh0,
        W_ih1, b_ih1, W_hh1, b_hh1, W_fc, b_fc, out);
}